// round 3
// baseline (speedup 1.0000x reference)
#include <cuda_runtime.h>
#include <math.h>

#define B_ 4
#define H_ 8
#define S_ 2048
#define D_ 16
#define QT 8            // queries per CTA
#define NT 512          // threads
#define ASTR 2052       // attn SMEM row stride (floats)
#define TDPS 2050       // tileDP row stride (float2 units) -> word stride 4100 = 4 mod 32 (conflict-free transposing STS.64)

typedef unsigned long long ull;

// SMEM float offsets
#define OFF_ATTN  0
#define OFF_TDP   (QT * ASTR)                    // 16416
#define OFF_SQ    (OFF_TDP + 8 * TDPS * 2)       // 49216
#define OFF_REDM  (OFF_SQ + 128)                 // 49344
#define OFF_REDS  (OFF_REDM + 144)               // 49488
#define OFF_SCTX  (OFF_REDS + 144)               // 49632 (even -> 8B aligned)
#define SMEM_FLOATS (OFF_SCTX + 1024)
#define SMEM_BYTES  (SMEM_FLOATS * 4)

__device__ __forceinline__ ull f2mul(ull a, ull b) {
    ull d; asm("mul.rn.f32x2 %0, %1, %2;" : "=l"(d) : "l"(a), "l"(b)); return d;
}
__device__ __forceinline__ ull f2fma(ull a, ull b, ull c) {
    ull d; asm("fma.rn.f32x2 %0, %1, %2, %3;" : "=l"(d) : "l"(a), "l"(b), "l"(c)); return d;
}
__device__ __forceinline__ ull f2add(ull a, ull b) {
    ull d; asm("add.rn.f32x2 %0, %1, %2;" : "=l"(d) : "l"(a), "l"(b)); return d;
}
__device__ __forceinline__ ull f2pack(float x, float y) {
    ull d; asm("mov.b64 %0, {%1, %2};" : "=l"(d) : "f"(x), "f"(y)); return d;
}
__device__ __forceinline__ float f2red(ull a) {
    float lo, hi; asm("mov.b64 {%0, %1}, %2;" : "=f"(lo), "=f"(hi) : "l"(a)); return lo + hi;
}

__global__ void __launch_bounds__(NT, 1)
sdpa_kernel(const float* __restrict__ Q, const float* __restrict__ K,
            const float* __restrict__ V, const int* __restrict__ mask,
            float* __restrict__ ctx_out, float* __restrict__ attn_out)
{
    extern __shared__ float sm[];
    float*  attnS  = sm + OFF_ATTN;                       // [QT][ASTR]
    float2* tileDP = (float2*)(sm + OFF_TDP);             // [8][TDPS]  pair (2d,2d+1) per key
    float*  sQ     = sm + OFF_SQ;                         // [QT*D_]
    float*  redm   = sm + OFF_REDM;                       // [16][9]
    float*  reds   = sm + OFF_REDS;                       // [16][9]
    ull*    sctx   = (ull*)(sm + OFF_SCTX);               // [16][32]

    const int h  = blockIdx.x;
    const int qt = blockIdx.y;
    const int b  = blockIdx.z;
    const int bh = b * H_ + h;

    const float* Qb = Q + (size_t)bh * S_ * D_;
    const float* Kb = K + (size_t)bh * S_ * D_;
    const float* Vb = V + (size_t)bh * S_ * D_;
    const int*   Mb = mask + (size_t)b * S_ * S_;

    const int tid  = threadIdx.x;
    const int lane = tid & 31;
    const int w    = tid >> 5;
    const int q0base = qt * QT;

    if (tid < QT * D_) sQ[tid] = Qb[(size_t)q0base * D_ + tid];
    __syncthreads();

    // ============ Phase A: scores in registers (thread = 4 keys x 8 q) ============
    // pass p covers keys {p*1024 + 2*tid, +1}
    float s[QT][4];
    float pmax[QT];
    #pragma unroll
    for (int q = 0; q < QT; ++q) pmax[q] = -INFINITY;

    #pragma unroll 1
    for (int p = 0; p < 2; ++p) {
        const int kp = p * 1024 + 2 * tid;
        const ulonglong2* Kp2 = (const ulonglong2*)(Kb + (size_t)kp * D_);
        ulonglong2 kv[8];   // rows kp (kv[0..3]) and kp+1 (kv[4..7]): 128B contiguous
        #pragma unroll
        for (int i = 0; i < 8; ++i) kv[i] = Kp2[i];

        #pragma unroll
        for (int q = 0; q < QT; ++q) {
            const ulonglong2* Qp2 = (const ulonglong2*)(sQ + q * D_);
            ulonglong2 qp0 = Qp2[0], qp1 = Qp2[1], qp2 = Qp2[2], qp3 = Qp2[3];
            ull accA = f2mul(kv[0].x, qp0.x);
            accA = f2fma(kv[0].y, qp0.y, accA);
            accA = f2fma(kv[1].x, qp1.x, accA);
            accA = f2fma(kv[1].y, qp1.y, accA);
            accA = f2fma(kv[2].x, qp2.x, accA);
            accA = f2fma(kv[2].y, qp2.y, accA);
            accA = f2fma(kv[3].x, qp3.x, accA);
            accA = f2fma(kv[3].y, qp3.y, accA);
            ull accB = f2mul(kv[4].x, qp0.x);
            accB = f2fma(kv[4].y, qp0.y, accB);
            accB = f2fma(kv[5].x, qp1.x, accB);
            accB = f2fma(kv[5].y, qp1.y, accB);
            accB = f2fma(kv[6].x, qp2.x, accB);
            accB = f2fma(kv[6].y, qp2.y, accB);
            accB = f2fma(kv[7].x, qp3.x, accB);
            accB = f2fma(kv[7].y, qp3.y, accB);
            const float dA = f2red(accA);
            const float dB = f2red(accB);
            const int2 m = *(const int2*)(Mb + (size_t)(q0base + q) * S_ + kp);
            const float sA = m.x ? -1e9f : dA * 0.25f;
            const float sB = m.y ? -1e9f : dB * 0.25f;
            s[q][2 * p + 0] = sA;
            s[q][2 * p + 1] = sB;
            pmax[q] = fmaxf(pmax[q], fmaxf(sA, sB));
        }
    }

    // ============ Stage V into packed-pair transposed tile (overlaps with B) ======
    #pragma unroll 1
    for (int i = 0; i < 16; ++i) {
        const int idx = i * NT + tid;           // 8192 float4 units
        const int row = idx >> 2, c = idx & 3;
        const float4 v = ((const float4*)(Vb + (size_t)row * D_))[c];
        tileDP[(2 * c + 0) * TDPS + row] = make_float2(v.x, v.y);
        tileDP[(2 * c + 1) * TDPS + row] = make_float2(v.z, v.w);
    }

    // ============ Phase B: softmax reductions ============
    #pragma unroll
    for (int q = 0; q < QT; ++q) {
        float v = pmax[q];
        #pragma unroll
        for (int o = 16; o > 0; o >>= 1) v = fmaxf(v, __shfl_xor_sync(0xffffffffu, v, o));
        pmax[q] = v;
    }
    if (lane == 0) {
        #pragma unroll
        for (int q = 0; q < QT; ++q) redm[w * 9 + q] = pmax[q];
    }
    __syncthreads();

    float mx[QT];
    #pragma unroll
    for (int q = 0; q < QT; ++q) {
        float v = (lane < 16) ? redm[lane * 9 + q] : -INFINITY;
        #pragma unroll
        for (int o = 8; o > 0; o >>= 1) v = fmaxf(v, __shfl_xor_sync(0xffffffffu, v, o));
        mx[q] = __shfl_sync(0xffffffffu, v, 0);
    }

    float psum[QT];
    #pragma unroll
    for (int q = 0; q < QT; ++q) {
        float e0 = __expf(s[q][0] - mx[q]);
        float e1 = __expf(s[q][1] - mx[q]);
        float e2 = __expf(s[q][2] - mx[q]);
        float e3 = __expf(s[q][3] - mx[q]);
        s[q][0] = e0; s[q][1] = e1; s[q][2] = e2; s[q][3] = e3;
        float t = (e0 + e1) + (e2 + e3);
        #pragma unroll
        for (int o = 16; o > 0; o >>= 1) t += __shfl_xor_sync(0xffffffffu, t, o);
        psum[q] = t;
    }
    if (lane == 0) {
        #pragma unroll
        for (int q = 0; q < QT; ++q) reds[w * 9 + q] = psum[q];
    }
    __syncthreads();

    // ============ normalize + write attn (global + SMEM) ============
    #pragma unroll
    for (int q = 0; q < QT; ++q) {
        float v = (lane < 16) ? reds[lane * 9 + q] : 0.0f;
        #pragma unroll
        for (int o = 8; o > 0; o >>= 1) v += __shfl_xor_sync(0xffffffffu, v, o);
        const float inv = 1.0f / __shfl_sync(0xffffffffu, v, 0);
        float2 e0 = make_float2(s[q][0] * inv, s[q][1] * inv);
        float2 e1 = make_float2(s[q][2] * inv, s[q][3] * inv);
        if (attn_out) {
            float* arow = attn_out + ((size_t)bh * S_ + q0base + q) * S_;
            *(float2*)(arow + 2 * tid)        = e0;
            *(float2*)(arow + 1024 + 2 * tid) = e1;
        }
        *(float2*)(attnS + q * ASTR + 2 * tid)        = e0;
        *(float2*)(attnS + q * ASTR + 1024 + 2 * tid) = e1;
    }
    __syncthreads();

    // ============ Phase C: ctx = attn @ V (warp = 4q x 256-key segment) ============
    const int qg  = w >> 3;        // q-group (0..1): queries qg*4 .. qg*4+3
    const int seg = w & 7;         // 256-key segment
    const int q0w = qg * 4;

    ull acc[4][8];
    #pragma unroll
    for (int qq = 0; qq < 4; ++qq)
        #pragma unroll
        for (int dp = 0; dp < 8; ++dp) acc[qq][dp] = 0ull;

    #pragma unroll 1
    for (int ch = 0; ch < 2; ++ch) {
        const int cb = seg * 256 + ch * 128 + lane;   // lane keys: cb + 32j
        ull a2[4][4];
        #pragma unroll
        for (int qq = 0; qq < 4; ++qq) {
            const float* ar = attnS + (q0w + qq) * ASTR + cb;
            #pragma unroll
            for (int j = 0; j < 4; ++j) {
                const float a = ar[32 * j];
                a2[qq][j] = f2pack(a, a);
            }
        }
        #pragma unroll
        for (int dp = 0; dp < 8; ++dp) {
            const ull* vr = (const ull*)(tileDP + dp * TDPS + cb);
            const ull v0 = vr[0], v1 = vr[32], v2 = vr[64], v3 = vr[96];
            #pragma unroll
            for (int qq = 0; qq < 4; ++qq) {
                acc[qq][dp] = f2fma(a2[qq][0], v0, acc[qq][dp]);
                acc[qq][dp] = f2fma(a2[qq][1], v1, acc[qq][dp]);
                acc[qq][dp] = f2fma(a2[qq][2], v2, acc[qq][dp]);
                acc[qq][dp] = f2fma(a2[qq][3], v3, acc[qq][dp]);
            }
        }
    }

    // lane-reduce (packed adds), then deposit one u64 per lane
    #pragma unroll
    for (int qq = 0; qq < 4; ++qq)
        #pragma unroll
        for (int dp = 0; dp < 8; ++dp) {
            ull v = acc[qq][dp];
            #pragma unroll
            for (int o = 16; o > 0; o >>= 1)
                v = f2add(v, __shfl_xor_sync(0xffffffffu, v, o));
            acc[qq][dp] = v;
        }
    {
        ull mine = 0ull;
        #pragma unroll
        for (int l = 0; l < 32; ++l)
            if (lane == l) mine = acc[l >> 3][l & 7];
        sctx[w * 32 + lane] = mine;
    }
    __syncthreads();

    // ============ combine segments + store ctx ============
    if (ctx_out && tid < QT * D_) {
        const int q = tid >> 4, d = tid & 15;
        const int qg2 = q >> 2, qq = q & 3, dp = d >> 1, hi = d & 1;
        const float* sf = (const float*)sctx;
        float acc2 = 0.0f;
        #pragma unroll
        for (int sg = 0; sg < 8; ++sg)
            acc2 += sf[((qg2 * 8 + sg) * 32 + qq * 8 + dp) * 2 + hi];
        ctx_out[((size_t)bh * S_ + q0base + q) * D_ + d] = acc2;
    }
}

extern "C" void kernel_launch(void* const* d_in, const int* in_sizes, int n_in,
                              void* d_out, int out_size)
{
    const float* Q    = (const float*)d_in[0];
    const float* K    = (const float*)d_in[1];
    const float* V    = (const float*)d_in[2];
    const int*   mask = (const int*)d_in[3];

    const long long CTX = (long long)B_ * H_ * S_ * D_;        // 1,048,576
    const long long ATT = (long long)B_ * H_ * S_ * S_;        // 134,217,728

    float* out  = (float*)d_out;
    float* ctx  = nullptr;
    float* attn = nullptr;
    if ((long long)out_size == CTX + ATT)      { ctx = out; attn = out + CTX; }
    else if ((long long)out_size == ATT)       { attn = out; }
    else if ((long long)out_size == CTX)       { ctx = out; }
    else                                       { ctx = out; if ((long long)out_size >= CTX + ATT) attn = out + CTX; }

    cudaFuncSetAttribute(sdpa_kernel, cudaFuncAttributeMaxDynamicSharedMemorySize, SMEM_BYTES);

    dim3 grid(H_, S_ / QT, B_);   // heads fastest -> mask rows reused in L2 across the 8 heads
    sdpa_kernel<<<grid, NT, SMEM_BYTES>>>(Q, K, V, mask, ctx, attn);
}